// round 12
// baseline (speedup 1.0000x reference)
#include <cuda_runtime.h>
#include <math.h>

#define D       128
#define NTRAIN  32768
#define NB      4096

typedef unsigned long long u64;

// ---- smem float offsets ----
#define OFF_W    0               // weight pairs [kp][j] u64: 16384 floats
#define OFF_B    16384           // 3 layer biases: l*128 + j (384)
#define OFF_W4P  16768           // W4 pairs [q][kp]: q*128 + 2kp (512)
#define OFF_B4   17280           // 8
#define OFF_TA   17288           // track buffer A: 4 trk x 16 pt x 132 = 8448
#define OFF_TB   25736           // track buffer B: 8448 (contiguous after A)
#define OFF_STG  34184           // staging 512
#define SM_FLOATS (34184 + 512)
#define SM_BYTES  (SM_FLOATS*4)  // 138784

#define TS16     2112            // 16 pts * 132 floats (one track)

// mu-net smem offsets (mu blocks only; live in weight region)
#define MUV1 0
#define MUV0 4096
#define MUC0 4224
#define MUC1 4288
#define MUV2 4352
#define MUC2 4416

#define TH      512
#define NPHYS   (NTRAIN/16)     // 2048
#define NBND    (4*(NB/128))    // 128
#define NMU     (NTRAIN/128)    // 256

// scratch (static device globals — no allocations)
__device__ float g_fluxlap[NTRAIN*8];
__device__ float g_mu[NTRAIN];
__device__ float g_bnd[NBND];            // 128
__device__ float g_comb[NTRAIN/512];     // 64

// ---------------------------------------------------------------------------
__device__ __forceinline__ u64 pk2(float lo, float hi) {
    u64 r; asm("mov.b64 %0, {%1, %2};" : "=l"(r) : "f"(lo), "f"(hi)); return r;
}
__device__ __forceinline__ void upk2(u64 v, float& lo, float& hi) {
    asm("mov.b64 {%0, %1}, %2;" : "=f"(lo), "=f"(hi) : "l"(v));
}
__device__ __forceinline__ void fma2(u64& d, u64 a, u64 b) {
    asm("fma.rn.f32x2 %0, %1, %2, %0;" : "+l"(d) : "l"(a), "l"(b));
}
__device__ __forceinline__ float hadd(u64 v) {
    float lo, hi; upk2(v, lo, hi); return lo + hi;
}
__device__ __forceinline__ float ftanh(float x) {
    float e = __expf(2.f*x);
    return 1.f - __fdividef(2.f, e + 1.f);
}

// stage 128x128 weights from gmem [k][j] into smem k-pair layout [kp][j] (u64)
__device__ __forceinline__ void stage_weights(float* sm, const float* __restrict__ Wg,
                                              int tid)
{
#pragma unroll
    for (int it = 0; it < 16; ++it) {
        int idx = tid + it*TH;          // 0..8191 pair slots
        int kp = idx >> 7, j = idx & 127;
        *reinterpret_cast<u64*>(sm + OFF_W + kp*256 + 2*j) =
            pk2(__ldg(Wg + (2*kp)*128 + j), __ldg(Wg + (2*kp+1)*128 + j));
    }
}

// ---------------------------------------------------------------------------
// Fused kernel, 512 threads, 1 CTA/SM.
//   [0,2048):     physics — 4 tracks split across 2 warp-groups, 16 pts/block
//   [2048,2176):  boundary — value only, 128 pts/block, in-place
//   [2176,2432):  mu-net — 128 pts/block, 4 slices of 16 units
// ---------------------------------------------------------------------------
__global__ void __launch_bounds__(TH, 1)
pinn_fused_kernel(const float* __restrict__ x_train,
                  const float* __restrict__ x_inlet, const float* __restrict__ U_inlet,
                  const float* __restrict__ x_base,  const float* __restrict__ x_top,
                  const float* __restrict__ x_slip,
                  const float* __restrict__ W0, const float* __restrict__ b0v,
                  const float* __restrict__ W1, const float* __restrict__ b1v,
                  const float* __restrict__ W2, const float* __restrict__ b2v,
                  const float* __restrict__ W3, const float* __restrict__ b3v,
                  const float* __restrict__ W4, const float* __restrict__ b4v,
                  const float* __restrict__ V0, const float* __restrict__ c0v,
                  const float* __restrict__ V1, const float* __restrict__ c1v,
                  const float* __restrict__ V2, const float* __restrict__ c2v)
{
    extern __shared__ float sm[];
    const int tid = threadIdx.x;
    const int cg  = tid & 15;       // column group (16 x 8 cols)
    const int bid = blockIdx.x;

    const float* Wl[3] = {W1, W2, W3};
    const float* bl[3] = {b1v, b2v, b3v};

    if (bid < NPHYS) {
        // ===================== PHYSICS (16 pts) =====================
        const int p0 = bid * 16;
        const int pg = (tid >> 4) & 15;   // point
        const int tg = tid >> 8;          // 0: tracks v,x  1: tracks y,L

        // pre-stage all biases + W4 pairs (once)
        if (tid < 384) {
            int l = tid >> 7, j = tid & 127;
            sm[OFF_B + l*128 + j] = __ldg(bl[l] + j);
        } else if (tid < 388) {
            sm[OFF_B4 + tid - 384] = __ldg(b4v + tid - 384);
        }
        if (tid < 256) {
            int q = tid & 3, kp = tid >> 2;
            *reinterpret_cast<u64*>(sm + OFF_W4P + q*128 + 2*kp) =
                pk2(__ldg(W4 + kp*8 + q), __ldg(W4 + kp*8 + 4 + q));
        }

        // ---- input layer (2 -> 128), 4 tracks -> buffer A ----
        {
            int pt = tid >> 5, jb = tid & 31;
            float2 xy = reinterpret_cast<const float2*>(x_train)[p0 + pt];
#pragma unroll
            for (int jj = 0; jj < 4; ++jj) {
                int j = jb + 32*jj;
                float w0 = __ldg(W0 + j), w1 = __ldg(W0 + 128 + j), bb = __ldg(b0v + j);
                float z = fmaf(xy.x, w0, fmaf(xy.y, w1, bb));
                float a = ftanh(z);
                float s = 1.f - a*a;
                int o = OFF_TA + pt*132 + j;
                sm[o]          = a;
                sm[o + TS16]   = s*w0;
                sm[o + 2*TS16] = s*w1;
                sm[o + 3*TS16] = (-2.f*a*s)*(w0*w0 + w1*w1);
            }
        }

        int inoff = OFF_TA, outoff = OFF_TB;
        for (int l = 0; l < 3; ++l) {
            stage_weights(sm, Wl[l], tid);
            __syncthreads();          // weights + input tracks visible

            // ---- 2-track GEMM per warp-group: tile 1pt x 2trk x 8col ----
            u64 acc[2][8];
#pragma unroll
            for (int t = 0; t < 2; ++t)
#pragma unroll
                for (int jj = 0; jj < 8; ++jj) acc[t][jj] = 0ull;

            const float* tp = sm + inoff + (tg*2)*TS16 + pg*132;
            const float* wp = sm + OFF_W + 2*cg;
#pragma unroll 2
            for (int kp = 0; kp < 64; ++kp) {
                u64 a0 = *reinterpret_cast<const u64*>(tp);
                u64 a1 = *reinterpret_cast<const u64*>(tp + TS16);
#pragma unroll
                for (int jj = 0; jj < 8; ++jj) {
                    u64 w = *reinterpret_cast<const u64*>(wp + 32*jj);
                    fma2(acc[0][jj], a0, w);
                    fma2(acc[1][jj], a1, w);
                }
                tp += 2; wp += 256;
            }

            // write raw z to OUT buffer (own slots, no conflict)
#pragma unroll
            for (int t = 0; t < 2; ++t)
#pragma unroll
                for (int jj = 0; jj < 8; ++jj)
                    sm[outoff + (tg*2 + t)*TS16 + pg*132 + cg + 16*jj] =
                        hadd(acc[t][jj]);
            __syncthreads();          // all raw z visible

            // ---- unified in-place epilogue: 4 elems/thread ----
            const float* bias = sm + OFF_B + l*128;
#pragma unroll
            for (int r = 0; r < 4; ++r) {
                int idx = tid + TH*r;          // 0..2047
                int pt = idx >> 7, j = idx & 127;
                int o = outoff + pt*132 + j;
                float zv = sm[o] + bias[j];
                float zx = sm[o + TS16];
                float zy = sm[o + 2*TS16];
                float zl = sm[o + 3*TS16];
                float a = ftanh(zv);
                float s = 1.f - a*a;
                sm[o]          = a;
                sm[o + TS16]   = s*zx;
                sm[o + 2*TS16] = s*zy;
                sm[o + 3*TS16] = s*(zl - 2.f*a*(zx*zx + zy*zy));
            }
            // no sync here: next loop's stage_weights writes only OFF_W,
            // and the loop-top sync orders epilogue writes before next GEMM.
            int t = inoff; inoff = outoff; outoff = t;
        }
        __syncthreads();

        // ---- final layer (128 -> 4): 16 pts x 4 q x 4 trk = 256 dots ----
        if (tid < 256) {
            int p = tid & 15, q = (tid >> 4) & 3, t = tid >> 6;
            const float* tp = sm + inoff + t*TS16 + p*132;
            const float* wq = sm + OFF_W4P + q*128;
            u64 acc = 0ull;
#pragma unroll 4
            for (int kp = 0; kp < 64; ++kp)
                fma2(acc, *reinterpret_cast<const u64*>(tp + 2*kp),
                          *reinterpret_cast<const u64*>(wq + 2*kp));
            float d = hadd(acc) + (t == 0 ? sm[OFF_B4 + q] : 0.f);
            sm[OFF_STG + (t*4 + q)*16 + p] = d;
        }
        __syncthreads();

        // ---- flux + Laplacian terms ----
        if (tid < 16) {
            float v[4][4];
#pragma unroll
            for (int t = 0; t < 4; ++t)
#pragma unroll
                for (int qq = 0; qq < 4; ++qq)
                    v[t][qq] = sm[OFF_STG + (t*4 + qq)*16 + tid];

            float rho = v[0][0], P  = v[0][1], u  = v[0][2], w  = v[0][3];
            float rx  = v[1][0], Px = v[1][1], ux = v[1][2], wx = v[1][3];
            float ry  = v[2][0], Py = v[2][1], uy = v[2][2], wy = v[2][3];
            float rL  = v[3][0], PL = v[3][1], uL = v[3][2], wL = v[3][3];

            const float ig = 2.5f;
            float q2 = u*u + w*w;
            float kx = u*ux + w*wx;
            float ky = u*uy + w*wy;
            float E  = P*ig  + 0.5f*rho*q2;
            float Ex = Px*ig + 0.5f*rx*q2 + rho*kx;
            float Ey = Py*ig + 0.5f*ry*q2 + rho*ky;

            float F1 = rx*u + rho*ux + ry*w + rho*wy;
            float F2 = rx*u*u + 2.f*rho*u*ux + Px + ry*u*w + rho*(uy*w + u*wy);
            float F3 = rx*u*w + rho*(ux*w + u*wx) + ry*w*w + 2.f*rho*w*wy + Py;
            float F4 = ux*(E + P) + u*(Ex + Px) + wy*(E + P) + w*(Ey + Py);

            float L1 = rL;
            float L2 = rL*u + 2.f*(rx*ux + ry*uy) + rho*uL;
            float L3 = rL*w + 2.f*(rx*wx + ry*wy) + rho*wL;
            float L4 = PL*ig + 0.5f*rL*q2 + 2.f*(rx*kx + ry*ky)
                     + rho*(ux*ux + wx*wx + uy*uy + wy*wy + u*uL + w*wL);

            float4* out = reinterpret_cast<float4*>(g_fluxlap) + (p0 + tid)*2;
            out[0] = make_float4(F1, F2, F3, F4);
            out[1] = make_float4(L1, L2, L3, L4);
        }
    } else if (bid < NPHYS + NBND) {
        // ===================== BOUNDARY (128 pts, in-place) =================
        const int b2 = bid - NPHYS;            // 0..127
        const int set = b2 >> 5;
        const int pbase = (b2 & 31) * 128;
        const int pg = tid >> 4;               // 0..31
        const float* xp = (set == 0) ? x_inlet : (set == 1) ? x_base
                        : (set == 2) ? x_top   : x_slip;

        if (tid < 384) {
            int l = tid >> 7, j = tid & 127;
            sm[OFF_B + l*128 + j] = __ldg(bl[l] + j);
        } else if (tid < 388) {
            sm[OFF_B4 + tid - 384] = __ldg(b4v + tid - 384);
        }
        if (tid < 256) {
            int q = tid & 3, kp = tid >> 2;
            *reinterpret_cast<u64*>(sm + OFF_W4P + q*128 + 2*kp) =
                pk2(__ldg(W4 + kp*8 + q), __ldg(W4 + kp*8 + 4 + q));
        }

        // input layer (value only) -> single buffer at OFF_TA (16896 floats)
        {
            int pt = tid >> 2, jb = tid & 3;
            float2 xy = reinterpret_cast<const float2*>(xp)[pbase + pt];
#pragma unroll
            for (int jj = 0; jj < 32; ++jj) {
                int j = jb + 4*jj;
                float w0 = __ldg(W0 + j), w1 = __ldg(W0 + 128 + j), bb = __ldg(b0v + j);
                sm[OFF_TA + pt*132 + j] = ftanh(fmaf(xy.x, w0, fmaf(xy.y, w1, bb)));
            }
        }

        for (int l = 0; l < 3; ++l) {
            stage_weights(sm, Wl[l], tid);
            __syncthreads();

            u64 acc[4][8];
#pragma unroll
            for (int i = 0; i < 4; ++i)
#pragma unroll
                for (int jj = 0; jj < 8; ++jj) acc[i][jj] = 0ull;

            const float* tp = sm + OFF_TA + pg*132;  // pts pg+32i
            const float* wp = sm + OFF_W + 2*cg;
#pragma unroll 2
            for (int kp = 0; kp < 64; ++kp) {
                u64 a0 = *reinterpret_cast<const u64*>(tp);
                u64 a1 = *reinterpret_cast<const u64*>(tp + 32*132);
                u64 a2 = *reinterpret_cast<const u64*>(tp + 64*132);
                u64 a3 = *reinterpret_cast<const u64*>(tp + 96*132);
#pragma unroll
                for (int jj = 0; jj < 8; ++jj) {
                    u64 w = *reinterpret_cast<const u64*>(wp + 32*jj);
                    fma2(acc[0][jj], a0, w);
                    fma2(acc[1][jj], a1, w);
                    fma2(acc[2][jj], a2, w);
                    fma2(acc[3][jj], a3, w);
                }
                tp += 2; wp += 256;
            }
            __syncthreads();          // all reads done -> safe to overwrite

            const float* bias = sm + OFF_B + l*128;
#pragma unroll
            for (int i = 0; i < 4; ++i) {
                int pt = pg + 32*i;
#pragma unroll
                for (int jj = 0; jj < 8; ++jj) {
                    int j = cg + 16*jj;
                    sm[OFF_TA + pt*132 + j] = ftanh(hadd(acc[i][jj]) + bias[j]);
                }
            }
            __syncthreads();
        }

        // final layer (value only): 128 pts x 4 outputs
        {
            int p = tid & 127, q = tid >> 7;
            const float* tp = sm + OFF_TA + p*132;
            const float* wq = sm + OFF_W4P + q*128;
            u64 acc = 0ull;
#pragma unroll 4
            for (int kp = 0; kp < 64; ++kp)
                fma2(acc, *reinterpret_cast<const u64*>(tp + 2*kp),
                          *reinterpret_cast<const u64*>(wq + 2*kp));
            sm[OFF_STG + q*128 + p] = hadd(acc) + sm[OFF_B4 + q];
        }
        __syncthreads();

        if (tid < 128) {
            float o0 = sm[OFF_STG + 0*128 + tid], o1 = sm[OFF_STG + 1*128 + tid];
            float o2 = sm[OFF_STG + 2*128 + tid], o3 = sm[OFF_STG + 3*128 + tid];
            float c;
            if (set == 0) {
                const float* Up = U_inlet + (pbase + tid)*4;
                float d0 = o0 - Up[0], d1 = o1 - Up[1];
                float d2 = o2 - Up[2], d3 = o3 - Up[3];
                c = d0*d0 + d1*d1 + d2*d2 + d3*d3;
            } else if (set == 3) {
                const float sa = -0.17364817766693033f;   // sin(-pi/18)
                const float ca =  0.98480775301220800f;   // cos(-pi/18)
                float t = -o2*sa + o3*ca;
                c = t*t;
            } else {
                c = o3*o3;
            }
            sm[OFF_TA + tid] = c;     // reuse track area for reduction
        }
        __syncthreads();
        if (tid < 32) {
            float vv = sm[OFF_TA + tid]      + sm[OFF_TA + tid + 32]
                     + sm[OFF_TA + tid + 64] + sm[OFF_TA + tid + 96];
#pragma unroll
            for (int o = 16; o > 0; o >>= 1)
                vv += __shfl_down_sync(0xffffffff, vv, o);
            if (tid == 0) g_bnd[b2] = vv;
        }
    } else {
        // ===================== MU (128 pts/block, 4 slices of 16) ===========
        const int mb = bid - (NPHYS + NBND);   // 0..255
#pragma unroll
        for (int it = 0; it < 8; ++it)
            sm[MUV1 + tid + it*TH] = __ldg(V1 + tid + it*TH);
        if (tid < 128) sm[MUV0 + tid] = __ldg(V0 + tid);
        else if (tid < 192) sm[MUC0 + tid - 128] = __ldg(c0v + tid - 128);
        else if (tid < 256) sm[MUC1 + tid - 192] = __ldg(c1v + tid - 192);
        else if (tid < 320) sm[MUV2 + tid - 256] = __ldg(V2 + tid - 256);
        else if (tid == 320) sm[MUC2] = __ldg(c2v);
        __syncthreads();

        const int p = tid >> 2;       // point 0..127
        const int s = tid & 3;        // slice (16 units)
        float2 xy = reinterpret_cast<const float2*>(x_train)[mb*128 + p];
#pragma unroll
        for (int uu = 0; uu < 16; ++uu) {
            int u = s*16 + uu;
            float z = fmaf(xy.x, sm[MUV0 + u], fmaf(xy.y, sm[MUV0 + 64 + u], sm[MUC0 + u]));
            sm[OFF_TA + u*132 + p] = ftanh(z);    // h1T[u][p]
        }
        __syncthreads();

        float zacc[16];
#pragma unroll
        for (int uu = 0; uu < 16; ++uu) zacc[uu] = sm[MUC1 + s*16 + uu];
#pragma unroll 2
        for (int k = 0; k < 64; ++k) {
            float h = sm[OFF_TA + k*132 + p];
#pragma unroll
            for (int f4 = 0; f4 < 4; ++f4) {
                float4 v = *reinterpret_cast<const float4*>(sm + MUV1 + k*64 + s*16 + f4*4);
                zacc[f4*4+0] = fmaf(h, v.x, zacc[f4*4+0]);
                zacc[f4*4+1] = fmaf(h, v.y, zacc[f4*4+1]);
                zacc[f4*4+2] = fmaf(h, v.z, zacc[f4*4+2]);
                zacc[f4*4+3] = fmaf(h, v.w, zacc[f4*4+3]);
            }
        }
        float o = (s == 0) ? sm[MUC2] : 0.f;
#pragma unroll
        for (int uu = 0; uu < 16; ++uu)
            o = fmaf(ftanh(zacc[uu]), sm[MUV2 + s*16 + uu], o);
        o += __shfl_xor_sync(0xffffffff, o, 1, 4);
        o += __shfl_xor_sync(0xffffffff, o, 2, 4);
        if (s == 0) g_mu[mb*128 + p] = 0.01f * o * o;
    }
}

// ---------------------------------------------------------------------------
__global__ void __launch_bounds__(512)
combine_kernel()
{
    __shared__ float red[512];
    const int tid = threadIdx.x;
    const int p = blockIdx.x*512 + tid;
    const float4* in = reinterpret_cast<const float4*>(g_fluxlap) + p*2;
    float4 fl = in[0];
    float4 lp = in[1];
    float mu = g_mu[p];
    float r1 = fl.x - mu*lp.x;
    float r2 = fl.y - mu*lp.y;
    float r3 = fl.z - mu*lp.z;
    float r4 = fl.w - mu*lp.w;
    red[tid] = r1*r1 + r2*r2 + r3*r3 + r4*r4 + 0.1f*mu*mu;
    __syncthreads();
    if (tid < 256) red[tid] += red[tid + 256];
    __syncthreads();
    if (tid < 128) red[tid] += red[tid + 128];
    __syncthreads();
    if (tid < 64) red[tid] += red[tid + 64];
    __syncthreads();
    if (tid < 32) {
        float vv = red[tid] + red[tid + 32];
#pragma unroll
        for (int o = 16; o > 0; o >>= 1)
            vv += __shfl_down_sync(0xffffffff, vv, o);
        if (tid == 0) g_comb[blockIdx.x] = vv;
    }
}

__global__ void __launch_bounds__(128)
reduce_kernel(float* __restrict__ out)
{
    __shared__ float red[128];
    const int tid = threadIdx.x;
    float a = g_bnd[tid] * (10.f / 4096.f);
    if (tid < 64) a += g_comb[tid] * (1.f / 32768.f);
    red[tid] = a;
    __syncthreads();
    if (tid < 64) red[tid] += red[tid + 64];
    __syncthreads();
    if (tid < 32) {
        float vv = red[tid] + red[tid + 32];
#pragma unroll
        for (int o = 16; o > 0; o >>= 1)
            vv += __shfl_down_sync(0xffffffff, vv, o);
        if (tid == 0) out[0] = vv;
    }
}

// ---------------------------------------------------------------------------
extern "C" void kernel_launch(void* const* d_in, const int* in_sizes, int n_in,
                              void* d_out, int out_size)
{
    const float* x_train = (const float*)d_in[0];
    const float* x_inlet = (const float*)d_in[1];
    const float* U_inlet = (const float*)d_in[2];
    const float* x_base  = (const float*)d_in[3];
    const float* x_top   = (const float*)d_in[4];
    const float* x_slip  = (const float*)d_in[5];
    const float* W0 = (const float*)d_in[6];  const float* b0 = (const float*)d_in[7];
    const float* W1 = (const float*)d_in[8];  const float* b1 = (const float*)d_in[9];
    const float* W2 = (const float*)d_in[10]; const float* b2 = (const float*)d_in[11];
    const float* W3 = (const float*)d_in[12]; const float* b3 = (const float*)d_in[13];
    const float* W4 = (const float*)d_in[14]; const float* b4 = (const float*)d_in[15];
    const float* V0 = (const float*)d_in[16]; const float* c0 = (const float*)d_in[17];
    const float* V1 = (const float*)d_in[18]; const float* c1 = (const float*)d_in[19];
    const float* V2 = (const float*)d_in[20]; const float* c2 = (const float*)d_in[21];

    cudaFuncSetAttribute(pinn_fused_kernel,
                         cudaFuncAttributeMaxDynamicSharedMemorySize, SM_BYTES);

    pinn_fused_kernel<<<NPHYS + NBND + NMU, TH, SM_BYTES>>>(x_train,
        x_inlet, U_inlet, x_base, x_top, x_slip,
        W0, b0, W1, b1, W2, b2, W3, b3, W4, b4,
        V0, c0, V1, c1, V2, c2);
    combine_kernel<<<NTRAIN/512, 512>>>();
    reduce_kernel<<<1, 128>>>((float*)d_out);
}

// round 13
// speedup vs baseline: 1.4287x; 1.4287x over previous
#include <cuda_runtime.h>
#include <math.h>

#define D       128
#define NTRAIN  32768
#define NB      4096

typedef unsigned long long u64;

// ---- smem float offsets ----
#define OFF_WP   0                       // weight pairs [kp][j] u64: 16384 floats
#define OFF_T    16384                   // tracks: t*TSTRIDE + pt*132 + k
#define TSTRIDE  8448                    // floats per track (64 pts x 132)
#define OFF_B    (OFF_T + 4*TSTRIDE)     // 50176: bias 128
#define OFF_W4P  (OFF_B + 128)           // 50304: W4 pairs [q][kp]: q*128+2kp
#define OFF_B4   (OFF_W4P + 512)         // 50816
#define OFF_STG  (OFF_B4 + 8)            // 50824: staging (<=1024 floats)
#define SM_FLOATS (OFF_STG + 1024)
#define SM_BYTES  (SM_FLOATS*4)          // 207392

// mu-net staging offsets (mu blocks only, inside weight region)
#define MUV0 (OFF_WP + 4096)
#define MUC0 (OFF_WP + 4224)
#define MUC1 (OFF_WP + 4288)
#define MUV2 (OFF_WP + 4352)
#define MUC2 (OFF_WP + 4416)

#define TH       512
#define NPHYS    (NTRAIN/64)    // 512
#define NBND     (4*(NB/128))   // 128
#define NMU      (NTRAIN/128)   // 256

// scratch (static device globals — no allocations)
__device__ float g_fluxlap[NTRAIN*8];
__device__ float g_mu[NTRAIN];
__device__ float g_bnd[NBND];            // 128
__device__ float g_comb[NTRAIN/512];     // 64

// ---------------------------------------------------------------------------
__device__ __forceinline__ u64 pk2(float lo, float hi) {
    u64 r; asm("mov.b64 %0, {%1, %2};" : "=l"(r) : "f"(lo), "f"(hi)); return r;
}
__device__ __forceinline__ void upk2(u64 v, float& lo, float& hi) {
    asm("mov.b64 {%0, %1}, %2;" : "=f"(lo), "=f"(hi) : "l"(v));
}
__device__ __forceinline__ void fma2(u64& d, u64 a, u64 b) {
    asm("fma.rn.f32x2 %0, %1, %2, %0;" : "+l"(d) : "l"(a), "l"(b));
}
__device__ __forceinline__ float hadd(u64 v) {
    float lo, hi; upk2(v, lo, hi); return lo + hi;
}
// fast tanh via __expf (rel err ~1e-6, graceful at +-inf)
__device__ __forceinline__ float ftanh(float x) {
    float e = __expf(2.f*x);
    return 1.f - __fdividef(2.f, e + 1.f);
}

// stage 128x128 weights from gmem [k][j] into smem k-pair layout [kp][j] (u64)
__device__ __forceinline__ void stage_weights(float* sm, const float* __restrict__ Wg,
                                              const float* __restrict__ bg, int tid)
{
#pragma unroll
    for (int it = 0; it < 16; ++it) {
        int idx = tid + it*TH;
        int kp = idx >> 7, j = idx & 127;
        float w0 = __ldg(Wg + kp*256 + j);
        float w1 = __ldg(Wg + kp*256 + 128 + j);
        *reinterpret_cast<u64*>(sm + OFF_WP + kp*256 + 2*j) = pk2(w0, w1);
    }
    if (tid < 128) sm[OFF_B + tid] = __ldg(bg + tid);
}

// fused 2-track GEMM pass over k-pairs: tile 2 pts x 2 tracks x 8 cols.
// acc u64 holds (even-k partial, odd-k partial).
template<int TAOFF, int TBOFF>
__device__ __forceinline__ void gemm_pass(const float* __restrict__ sm, int pg, int cg,
                                          u64 accA[2][8], u64 accB[2][8])
{
#pragma unroll
    for (int i = 0; i < 2; ++i)
#pragma unroll
        for (int jj = 0; jj < 8; ++jj) { accA[i][jj] = 0ull; accB[i][jj] = 0ull; }

    const float* tp = sm + OFF_T + TAOFF + (2*pg)*132;
    const float* wp = sm + OFF_WP + 2*cg;
#pragma unroll 2
    for (int kp = 0; kp < 64; ++kp) {
        u64 a0 = *reinterpret_cast<const u64*>(tp);
        u64 a1 = *reinterpret_cast<const u64*>(tp + 132);
        u64 b0 = *reinterpret_cast<const u64*>(tp + (TBOFF - TAOFF));
        u64 b1 = *reinterpret_cast<const u64*>(tp + (TBOFF - TAOFF) + 132);
#pragma unroll
        for (int jj = 0; jj < 8; ++jj) {
            u64 w = *reinterpret_cast<const u64*>(wp + 32*jj);
            fma2(accA[0][jj], a0, w);
            fma2(accA[1][jj], a1, w);
            fma2(accB[0][jj], b0, w);
            fma2(accB[1][jj], b1, w);
        }
        tp += 2; wp += 256;
    }
}

// ---------------------------------------------------------------------------
// Fused kernel, 512 threads.
//   [0,512):   physics — tracks (val,dx,dy,Lap), 64 pts/block
//   [512,640): boundary — value only, 128 pts/block
//   [640,896): mu-net — 128 pts/block, 4 slices of 16 units
// Track rows of a pt-pair are read/written exclusively by one half-warp, so
// GEMM<->epilogue hazards need only __syncwarp(); block barriers bracket only
// the shared weight staging.
// ---------------------------------------------------------------------------
__global__ void __launch_bounds__(TH, 1)
pinn_fused_kernel(const float* __restrict__ x_train,
                  const float* __restrict__ x_inlet, const float* __restrict__ U_inlet,
                  const float* __restrict__ x_base,  const float* __restrict__ x_top,
                  const float* __restrict__ x_slip,
                  const float* __restrict__ W0, const float* __restrict__ b0v,
                  const float* __restrict__ W1, const float* __restrict__ b1v,
                  const float* __restrict__ W2, const float* __restrict__ b2v,
                  const float* __restrict__ W3, const float* __restrict__ b3v,
                  const float* __restrict__ W4, const float* __restrict__ b4v,
                  const float* __restrict__ V0, const float* __restrict__ c0v,
                  const float* __restrict__ V1, const float* __restrict__ c1v,
                  const float* __restrict__ V2, const float* __restrict__ c2v)
{
    extern __shared__ float sm[];
    const int tid = threadIdx.x;
    const int cg  = tid & 15;
    const int pg  = tid >> 4;
    const int bid = blockIdx.x;

    const float* Wl[3] = {W1, W2, W3};
    const float* bl[3] = {b1v, b2v, b3v};

    if (bid < NPHYS) {
        // ===================== PHYSICS =====================
        const int p0 = bid * 64;

        // stage W4 pairs + b4
        if (tid < 256) {
            int q = tid & 3, kp = tid >> 2;
            *reinterpret_cast<u64*>(sm + OFF_W4P + q*128 + 2*kp) =
                pk2(__ldg(W4 + kp*8 + q), __ldg(W4 + kp*8 + 4 + q));
        } else if (tid < 260) {
            sm[OFF_B4 + tid - 256] = __ldg(b4v + tid - 256);
        }

        // ---- input layer (2 -> 128), 4 tracks, [pt][k] layout ----
        {
            int pt = tid >> 3, jb = tid & 7;
            float2 xy = reinterpret_cast<const float2*>(x_train)[p0 + pt];
#pragma unroll
            for (int jj = 0; jj < 16; ++jj) {
                int j = jb + 8*jj;
                float w0 = __ldg(W0 + j), w1 = __ldg(W0 + 128 + j), bb = __ldg(b0v + j);
                float z = fmaf(xy.x, w0, fmaf(xy.y, w1, bb));
                float a = ftanh(z);
                float s = 1.f - a*a;
                int o = OFF_T + pt*132 + j;
                sm[o]             = a;
                sm[o + TSTRIDE]   = s*w0;
                sm[o + 2*TSTRIDE] = s*w1;
                sm[o + 3*TSTRIDE] = (-2.f*a*s)*(w0*w0 + w1*w1);
            }
        }

        for (int l = 0; l < 3; ++l) {
            __syncthreads();                       // prev layer done with weights
            stage_weights(sm, Wl[l], bl[l], tid);
            __syncthreads();                       // weights + tracks visible

            u64 accA[2][8], accB[2][8];
            gemm_pass<0, TSTRIDE>(sm, pg, cg, accA, accB);   // tracks v, x
            __syncwarp();     // half-warp-local rows: warp sync suffices

            // epi1: new a into track0, raw zx into track1
#pragma unroll
            for (int i = 0; i < 2; ++i) {
                int pt = 2*pg + i;
#pragma unroll
                for (int jj = 0; jj < 8; ++jj) {
                    int j = cg + 16*jj;
                    float zv = hadd(accA[i][jj]) + sm[OFF_B + j];
                    float zx = hadd(accB[i][jj]);
                    int o = OFF_T + pt*132 + j;
                    sm[o]           = ftanh(zv);
                    sm[o + TSTRIDE] = zx;
                }
            }
            __syncwarp();
            gemm_pass<2*TSTRIDE, 3*TSTRIDE>(sm, pg, cg, accA, accB);  // y, L
            __syncwarp();

            // epi2: finish x, y, Lap (reads own a/zx written in epi1)
#pragma unroll
            for (int i = 0; i < 2; ++i) {
                int pt = 2*pg + i;
#pragma unroll
                for (int jj = 0; jj < 8; ++jj) {
                    int j = cg + 16*jj;
                    int o = OFF_T + pt*132 + j;
                    float zy = hadd(accA[i][jj]);
                    float zl = hadd(accB[i][jj]);
                    float a  = sm[o];
                    float zx = sm[o + TSTRIDE];
                    float s  = 1.f - a*a;
                    sm[o + TSTRIDE]   = s*zx;
                    sm[o + 2*TSTRIDE] = s*zy;
                    sm[o + 3*TSTRIDE] = s*(zl - 2.f*a*(zx*zx + zy*zy));
                }
            }
        }
        __syncthreads();

        // ---- final layer (128 -> 4), all 4 tracks ----
        {
            int p = tid & 63, q = (tid >> 6) & 3, th = tid >> 8;
#pragma unroll
            for (int tt = 0; tt < 2; ++tt) {
                int t = th + 2*tt;
                const float* tp = sm + OFF_T + t*TSTRIDE + p*132;
                const float* wq = sm + OFF_W4P + q*128;
                u64 acc = 0ull;
#pragma unroll 4
                for (int kp = 0; kp < 64; ++kp)
                    fma2(acc, *reinterpret_cast<const u64*>(tp + 2*kp),
                              *reinterpret_cast<const u64*>(wq + 2*kp));
                float d = hadd(acc) + (t == 0 ? sm[OFF_B4 + q] : 0.f);
                sm[OFF_STG + (t*4 + q)*64 + p] = d;
            }
        }
        __syncthreads();

        // ---- flux + Laplacian terms ----
        if (tid < 64) {
            float v[4][4];
#pragma unroll
            for (int t = 0; t < 4; ++t)
#pragma unroll
                for (int qq = 0; qq < 4; ++qq)
                    v[t][qq] = sm[OFF_STG + (t*4 + qq)*64 + tid];

            float rho = v[0][0], P  = v[0][1], u  = v[0][2], w  = v[0][3];
            float rx  = v[1][0], Px = v[1][1], ux = v[1][2], wx = v[1][3];
            float ry  = v[2][0], Py = v[2][1], uy = v[2][2], wy = v[2][3];
            float rL  = v[3][0], PL = v[3][1], uL = v[3][2], wL = v[3][3];

            const float ig = 2.5f;
            float q2 = u*u + w*w;
            float kx = u*ux + w*wx;
            float ky = u*uy + w*wy;
            float E  = P*ig  + 0.5f*rho*q2;
            float Ex = Px*ig + 0.5f*rx*q2 + rho*kx;
            float Ey = Py*ig + 0.5f*ry*q2 + rho*ky;

            float F1 = rx*u + rho*ux + ry*w + rho*wy;
            float F2 = rx*u*u + 2.f*rho*u*ux + Px + ry*u*w + rho*(uy*w + u*wy);
            float F3 = rx*u*w + rho*(ux*w + u*wx) + ry*w*w + 2.f*rho*w*wy + Py;
            float F4 = ux*(E + P) + u*(Ex + Px) + wy*(E + P) + w*(Ey + Py);

            float L1 = rL;
            float L2 = rL*u + 2.f*(rx*ux + ry*uy) + rho*uL;
            float L3 = rL*w + 2.f*(rx*wx + ry*wy) + rho*wL;
            float L4 = PL*ig + 0.5f*rL*q2 + 2.f*(rx*kx + ry*ky)
                     + rho*(ux*ux + wx*wx + uy*uy + wy*wy + u*uL + w*wL);

            float4* out = reinterpret_cast<float4*>(g_fluxlap) + (p0 + tid)*2;
            out[0] = make_float4(F1, F2, F3, F4);
            out[1] = make_float4(L1, L2, L3, L4);
        }
    } else if (bid < NPHYS + NBND) {
        // ===================== BOUNDARY (128 pts/block) =====================
        const int b2 = bid - NPHYS;            // 0..127
        const int set = b2 >> 5;
        const int pbase = (b2 & 31) * 128;
        const float* xp = (set == 0) ? x_inlet : (set == 1) ? x_base
                        : (set == 2) ? x_top   : x_slip;

        if (tid < 256) {
            int q = tid & 3, kp = tid >> 2;
            *reinterpret_cast<u64*>(sm + OFF_W4P + q*128 + 2*kp) =
                pk2(__ldg(W4 + kp*8 + q), __ldg(W4 + kp*8 + 4 + q));
        } else if (tid < 260) {
            sm[OFF_B4 + tid - 256] = __ldg(b4v + tid - 256);
        }

        // input layer (value only)
        {
            int pt = tid >> 2, jb = tid & 3;
            float2 xy = reinterpret_cast<const float2*>(xp)[pbase + pt];
#pragma unroll
            for (int jj = 0; jj < 32; ++jj) {
                int j = jb + 4*jj;
                float w0 = __ldg(W0 + j), w1 = __ldg(W0 + 128 + j), bb = __ldg(b0v + j);
                sm[OFF_T + pt*132 + j] = ftanh(fmaf(xy.x, w0, fmaf(xy.y, w1, bb)));
            }
        }

        for (int l = 0; l < 3; ++l) {
            __syncthreads();
            stage_weights(sm, Wl[l], bl[l], tid);
            __syncthreads();

            u64 acc[4][8];
#pragma unroll
            for (int i = 0; i < 4; ++i)
#pragma unroll
                for (int jj = 0; jj < 8; ++jj) acc[i][jj] = 0ull;

            const float* tp = sm + OFF_T + pg*132;       // pts pg, pg+32, pg+64, pg+96
            const float* wp = sm + OFF_WP + 2*cg;
#pragma unroll 2
            for (int kp = 0; kp < 64; ++kp) {
                u64 a0 = *reinterpret_cast<const u64*>(tp);
                u64 a1 = *reinterpret_cast<const u64*>(tp + 32*132);
                u64 a2 = *reinterpret_cast<const u64*>(tp + 64*132);
                u64 a3 = *reinterpret_cast<const u64*>(tp + 96*132);
#pragma unroll
                for (int jj = 0; jj < 8; ++jj) {
                    u64 w = *reinterpret_cast<const u64*>(wp + 32*jj);
                    fma2(acc[0][jj], a0, w);
                    fma2(acc[1][jj], a1, w);
                    fma2(acc[2][jj], a2, w);
                    fma2(acc[3][jj], a3, w);
                }
                tp += 2; wp += 256;
            }
            __syncwarp();     // rows owned by this half-warp only
#pragma unroll
            for (int i = 0; i < 4; ++i) {
                int pt = pg + 32*i;
#pragma unroll
                for (int jj = 0; jj < 8; ++jj) {
                    int j = cg + 16*jj;
                    sm[OFF_T + pt*132 + j] = ftanh(hadd(acc[i][jj]) + sm[OFF_B + j]);
                }
            }
        }
        __syncthreads();

        // final layer (value only): 128 pts x 4 outputs
        {
            int p = tid & 127, q = tid >> 7;
            const float* tp = sm + OFF_T + p*132;
            const float* wq = sm + OFF_W4P + q*128;
            u64 acc = 0ull;
#pragma unroll 4
            for (int kp = 0; kp < 64; ++kp)
                fma2(acc, *reinterpret_cast<const u64*>(tp + 2*kp),
                          *reinterpret_cast<const u64*>(wq + 2*kp));
            sm[OFF_STG + q*128 + p] = hadd(acc) + sm[OFF_B4 + q];
        }
        __syncthreads();

        if (tid < 128) {
            float o0 = sm[OFF_STG + 0*128 + tid], o1 = sm[OFF_STG + 1*128 + tid];
            float o2 = sm[OFF_STG + 2*128 + tid], o3 = sm[OFF_STG + 3*128 + tid];
            float c;
            if (set == 0) {
                const float* Up = U_inlet + (pbase + tid)*4;
                float d0 = o0 - Up[0], d1 = o1 - Up[1];
                float d2 = o2 - Up[2], d3 = o3 - Up[3];
                c = d0*d0 + d1*d1 + d2*d2 + d3*d3;
            } else if (set == 3) {
                const float sa = -0.17364817766693033f;   // sin(-pi/18)
                const float ca =  0.98480775301220800f;   // cos(-pi/18)
                float t = -o2*sa + o3*ca;
                c = t*t;
            } else {
                c = o3*o3;
            }
            sm[OFF_STG + 512 + tid] = c;
        }
        __syncthreads();
        if (tid < 32) {
            float vv = sm[OFF_STG + 512 + tid]      + sm[OFF_STG + 512 + tid + 32]
                     + sm[OFF_STG + 512 + tid + 64] + sm[OFF_STG + 512 + tid + 96];
#pragma unroll
            for (int o = 16; o > 0; o >>= 1)
                vv += __shfl_down_sync(0xffffffff, vv, o);
            if (tid == 0) g_bnd[b2] = vv;
        }
    } else {
        // ===================== MU (128 pts/block, 4 slices of 16) ===========
        const int mb = bid - (NPHYS + NBND);   // 0..255
#pragma unroll
        for (int it = 0; it < 8; ++it)
            sm[OFF_WP + tid + it*TH] = __ldg(V1 + tid + it*TH);
        if (tid < 128) sm[MUV0 + tid] = __ldg(V0 + tid);
        else if (tid < 192) sm[MUC0 + tid - 128] = __ldg(c0v + tid - 128);
        else if (tid < 256) sm[MUC1 + tid - 192] = __ldg(c1v + tid - 192);
        else if (tid < 320) sm[MUV2 + tid - 256] = __ldg(V2 + tid - 256);
        else if (tid == 320) sm[MUC2] = __ldg(c2v);
        __syncthreads();

        const int p = tid >> 2;       // point 0..127
        const int s = tid & 3;        // slice (16 units)
        float2 xy = reinterpret_cast<const float2*>(x_train)[mb*128 + p];
#pragma unroll
        for (int uu = 0; uu < 16; ++uu) {
            int u = s*16 + uu;
            float z = fmaf(xy.x, sm[MUV0 + u], fmaf(xy.y, sm[MUV0 + 64 + u], sm[MUC0 + u]));
            sm[OFF_T + u*132 + p] = ftanh(z);    // h1T[u][p]
        }
        __syncthreads();

        float zacc[16];
#pragma unroll
        for (int uu = 0; uu < 16; ++uu) zacc[uu] = sm[MUC1 + s*16 + uu];
#pragma unroll 2
        for (int k = 0; k < 64; ++k) {
            float h = sm[OFF_T + k*132 + p];
#pragma unroll
            for (int f4 = 0; f4 < 4; ++f4) {
                float4 v = *reinterpret_cast<const float4*>(sm + OFF_WP + k*64 + s*16 + f4*4);
                zacc[f4*4+0] = fmaf(h, v.x, zacc[f4*4+0]);
                zacc[f4*4+1] = fmaf(h, v.y, zacc[f4*4+1]);
                zacc[f4*4+2] = fmaf(h, v.z, zacc[f4*4+2]);
                zacc[f4*4+3] = fmaf(h, v.w, zacc[f4*4+3]);
            }
        }
        float o = (s == 0) ? sm[MUC2] : 0.f;
#pragma unroll
        for (int uu = 0; uu < 16; ++uu)
            o = fmaf(ftanh(zacc[uu]), sm[MUV2 + s*16 + uu], o);
        o += __shfl_xor_sync(0xffffffff, o, 1, 4);
        o += __shfl_xor_sync(0xffffffff, o, 2, 4);
        if (s == 0) g_mu[mb*128 + p] = 0.01f * o * o;
    }
}

// ---------------------------------------------------------------------------
__global__ void __launch_bounds__(512)
combine_kernel()
{
    __shared__ float red[512];
    const int tid = threadIdx.x;
    const int p = blockIdx.x*512 + tid;
    const float4* in = reinterpret_cast<const float4*>(g_fluxlap) + p*2;
    float4 fl = in[0];
    float4 lp = in[1];
    float mu = g_mu[p];
    float r1 = fl.x - mu*lp.x;
    float r2 = fl.y - mu*lp.y;
    float r3 = fl.z - mu*lp.z;
    float r4 = fl.w - mu*lp.w;
    red[tid] = r1*r1 + r2*r2 + r3*r3 + r4*r4 + 0.1f*mu*mu;
    __syncthreads();
    if (tid < 256) red[tid] += red[tid + 256];
    __syncthreads();
    if (tid < 128) red[tid] += red[tid + 128];
    __syncthreads();
    if (tid < 64) red[tid] += red[tid + 64];
    __syncthreads();
    if (tid < 32) {
        float vv = red[tid] + red[tid + 32];
#pragma unroll
        for (int o = 16; o > 0; o >>= 1)
            vv += __shfl_down_sync(0xffffffff, vv, o);
        if (tid == 0) g_comb[blockIdx.x] = vv;
    }
}

__global__ void __launch_bounds__(128)
reduce_kernel(float* __restrict__ out)
{
    __shared__ float red[128];
    const int tid = threadIdx.x;
    float a = g_bnd[tid] * (10.f / 4096.f);
    if (tid < 64) a += g_comb[tid] * (1.f / 32768.f);
    red[tid] = a;
    __syncthreads();
    if (tid < 64) red[tid] += red[tid + 64];
    __syncthreads();
    if (tid < 32) {
        float vv = red[tid] + red[tid + 32];
#pragma unroll
        for (int o = 16; o > 0; o >>= 1)
            vv += __shfl_down_sync(0xffffffff, vv, o);
        if (tid == 0) out[0] = vv;
    }
}

// ---------------------------------------------------------------------------
extern "C" void kernel_launch(void* const* d_in, const int* in_sizes, int n_in,
                              void* d_out, int out_size)
{
    const float* x_train = (const float*)d_in[0];
    const float* x_inlet = (const float*)d_in[1];
    const float* U_inlet = (const float*)d_in[2];
    const float* x_base  = (const float*)d_in[3];
    const float* x_top   = (const float*)d_in[4];
    const float* x_slip  = (const float*)d_in[5];
    const float* W0 = (const float*)d_in[6];  const float* b0 = (const float*)d_in[7];
    const float* W1 = (const float*)d_in[8];  const float* b1 = (const float*)d_in[9];
    const float* W2 = (const float*)d_in[10]; const float* b2 = (const float*)d_in[11];
    const float* W3 = (const float*)d_in[12]; const float* b3 = (const float*)d_in[13];
    const float* W4 = (const float*)d_in[14]; const float* b4 = (const float*)d_in[15];
    const float* V0 = (const float*)d_in[16]; const float* c0 = (const float*)d_in[17];
    const float* V1 = (const float*)d_in[18]; const float* c1 = (const float*)d_in[19];
    const float* V2 = (const float*)d_in[20]; const float* c2 = (const float*)d_in[21];

    cudaFuncSetAttribute(pinn_fused_kernel,
                         cudaFuncAttributeMaxDynamicSharedMemorySize, SM_BYTES);

    pinn_fused_kernel<<<NPHYS + NBND + NMU, TH, SM_BYTES>>>(x_train,
        x_inlet, U_inlet, x_base, x_top, x_slip,
        W0, b0, W1, b1, W2, b2, W3, b3, W4, b4,
        V0, c0, V1, c1, V2, c2);
    combine_kernel<<<NTRAIN/512, 512>>>();
    reduce_kernel<<<1, 128>>>((float*)d_out);
}